// round 15
// baseline (speedup 1.0000x reference)
#include <cuda_runtime.h>
#include <cuda_fp16.h>
#include <math.h>
#include <stdint.h>

#define EPSV 1e-5f

// ---------------- static scratch ----------------
__device__ float g_buf1[512*24*38*38];
__device__ float g_buf2[512*24*19*19];
__device__ float g_buf3[512*24*10*10];
__device__ float g_buf4[512*24*5*5];
__device__ float g_part1[24*16];
__device__ float g_part2[24*16];
__device__ float g_scale[24];
__device__ float g_shift[24];
__device__ float g_U[512*25*256];
__device__ float g_V[512*25*256];
__device__ __half g_W2h[65536];
__device__ __half g_W3h[65536];
__device__ __half g_W4h[65536];
__device__ float g_P[5120*256];
__device__ float g_XG[512*256];
__device__ float g_F1[512*256];
__device__ float g_F2[512*256];
__device__ float g_FO[512*10];

// ---------------- helpers ----------------
__device__ __forceinline__ uint32_t smem_u32(const void* p) {
    uint32_t a;
    asm("{ .reg .u64 t; cvta.to.shared.u64 t, %1; cvt.u32.u64 %0, t; }" : "=r"(a) : "l"(p));
    return a;
}
__device__ __forceinline__ void cp_async16(uint32_t dst, const void* src) {
    asm volatile("cp.async.cg.shared.global [%0], [%1], 16;" :: "r"(dst), "l"(src));
}
__device__ __forceinline__ void cp_commit() { asm volatile("cp.async.commit_group;"); }
__device__ __forceinline__ void cp_wait0() { asm volatile("cp.async.wait_group 0;"); }
__device__ __forceinline__ void cp_wait1() { asm volatile("cp.async.wait_group 1;"); }

__device__ __forceinline__ void mma_f16(float* d, const uint32_t* a, const uint32_t* b) {
    asm volatile(
        "mma.sync.aligned.m16n8k16.row.col.f32.f16.f16.f32 "
        "{%0,%1,%2,%3}, {%4,%5,%6,%7}, {%8,%9}, {%0,%1,%2,%3};"
        : "+f"(d[0]), "+f"(d[1]), "+f"(d[2]), "+f"(d[3])
        : "r"(a[0]), "r"(a[1]), "r"(a[2]), "r"(a[3]), "r"(b[0]), "r"(b[1]));
}

// ---------------- weight conversion fp32 -> fp16 (one launch) ----------------
__global__ void w_to_half3(const float* __restrict__ a, const float* __restrict__ b,
                           const float* __restrict__ c,
                           __half* __restrict__ oa, __half* __restrict__ ob,
                           __half* __restrict__ oc) {
    int i = blockIdx.x * blockDim.x + threadIdx.x;
    if (i >= 3*65536) return;
    const float* src = (i < 65536) ? a : ((i < 131072) ? b : c);
    __half* dst = (i < 65536) ? oa : ((i < 131072) ? ob : oc);
    int off = i & 65535;
    dst[off] = __float2half_rn(src[off]);
}

// ---------------- conv: all planes resident, single sync ----------------
template<int CIN,int COUT,int HIN,int WIN,int HOUT,int WOUT,int NTHR,int P,int BNIN,int IMGS>
__global__ __launch_bounds__(NTHR)
void conv_res_kernel(const float* __restrict__ in, const float* __restrict__ w,
                     const float* __restrict__ bias,
                     const float* __restrict__ scale, const float* __restrict__ shift,
                     float* __restrict__ out) {
    extern __shared__ float cs[];
    float* planes = cs;
    float* wsm = cs + IMGS*CIN*HIN*WIN;
    const int tid = threadIdx.x;
    const int HW = HIN*WIN;
    const size_t gbase = (size_t)blockIdx.x * IMGS * CIN * HW;

    for (int i = tid; i < IMGS*CIN*HW; i += NTHR) {
        float v = in[gbase + i];
        if (BNIN) { int ci = (i / HW) % CIN; v = v*scale[ci] + shift[ci]; }
        planes[i] = v;
    }
    for (int i = tid; i < CIN*COUT*9; i += NTHR) {
        int ci = i / (COUT*9); int r = i % (COUT*9); int co = r/9, t = r%9;
        wsm[i] = w[(co*CIN+ci)*9 + t];
    }
    __syncthreads();

    const int OHW = HOUT*WOUT;
    #pragma unroll
    for (int p = 0; p < P; p++) {
        int pos = tid + p*NTHR;
        if (pos < IMGS*OHW) {
            int im = pos / OHW, pp = pos % OHW;
            int ho = pp / WOUT, wo = pp % WOUT;
            const float* pl = planes + im*CIN*HW;
            float acc[COUT];
            #pragma unroll
            for (int co = 0; co < COUT; co++) acc[co] = 0.f;
            for (int ci = 0; ci < CIN; ci++) {
                float win[9];
                #pragma unroll
                for (int kh = 0; kh < 3; kh++)
                    #pragma unroll
                    for (int kw = 0; kw < 3; kw++) {
                        int hi = ho*2-1+kh, wi = wo*2-1+kw;
                        win[kh*3+kw] = (hi>=0 && hi<HIN && wi>=0 && wi<WIN)
                                       ? pl[ci*HW + hi*WIN + wi] : 0.f;
                    }
                const float* wp = wsm + ci*COUT*9;
                #pragma unroll
                for (int co = 0; co < COUT; co++) {
                    float s = 0.f;
                    #pragma unroll
                    for (int t = 0; t < 9; t++) s += win[t]*wp[co*9+t];
                    acc[co] += s;
                }
            }
            size_t ob = ((size_t)(blockIdx.x*IMGS + im) * COUT) * OHW + pp;
            #pragma unroll
            for (int co = 0; co < COUT; co++)
                out[ob + (size_t)co*OHW] = fmaxf(acc[co] + bias[co], 0.f);
        }
    }
}

// ---------------- conv row-split: SPLITS CTAs per image ----------------
template<int CIN,int COUT,int HIN,int WIN,int HOUT,int WOUT,int NTHR,int SPLITS,int BNIN,int VEC>
__global__ __launch_bounds__(NTHR, 2)
void conv_split_kernel(const float* __restrict__ in, const float* __restrict__ w,
                       const float* __restrict__ bias,
                       const float* __restrict__ scale, const float* __restrict__ shift,
                       float* __restrict__ out) {
    constexpr int CEILR = (HOUT + SPLITS - 1) / SPLITS;
    constexpr int MAXR = 2*CEILR + 1;
    extern __shared__ float cs[];
    float* planes = cs;                      // CIN*MAXR*WIN
    float* wsm = cs + CIN*MAXR*WIN;          // CIN*COUT*9
    const int tid = threadIdx.x;
    const int b = blockIdx.x;
    const int sp = blockIdx.y;
    const int r0 = sp * CEILR;
    const int r1 = (r0 + CEILR < HOUT) ? (r0 + CEILR) : HOUT;
    const int gi0 = (2*r0 - 1 > 0) ? (2*r0 - 1) : 0;
    const int gi1 = (2*r1 < HIN) ? (2*r1) : HIN;
    const int NR = gi1 - gi0;
    const int HW = HIN*WIN;
    const int NRW = NR * WIN;

    const float* src0 = in + (size_t)b*CIN*HW + gi0*WIN;
    if (VEC) {
        const int NRW2 = NRW >> 1;
        for (int i = tid; i < CIN*NRW2; i += NTHR) {
            int ci = i / NRW2, rem = i - ci*NRW2;
            float2 v = *(const float2*)(src0 + (size_t)ci*HW + rem*2);
            if (BNIN) {
                float sc = scale[ci], sh = shift[ci];
                v.x = v.x*sc + sh; v.y = v.y*sc + sh;
            }
            *(float2*)(planes + ci*(MAXR*WIN) + rem*2) = v;
        }
    } else {
        for (int i = tid; i < CIN*NRW; i += NTHR) {
            int ci = i / NRW, rem = i - ci*NRW;
            float v = src0[(size_t)ci*HW + rem];
            if (BNIN) v = v*scale[ci] + shift[ci];
            planes[ci*(MAXR*WIN) + rem] = v;
        }
    }
    for (int i = tid; i < CIN*COUT*9; i += NTHR) {
        int ci = i / (COUT*9); int r = i % (COUT*9); int co = r/9, t = r%9;
        wsm[i] = w[(co*CIN+ci)*9 + t];
    }
    __syncthreads();

    const int nout = (r1 - r0) * WOUT;
    if (tid < nout) {
        int ho = r0 + tid / WOUT, wo = tid % WOUT;
        float acc[COUT];
        #pragma unroll
        for (int co = 0; co < COUT; co++) acc[co] = 0.f;
        for (int ci = 0; ci < CIN; ci++) {
            const float* pl = planes + ci*(MAXR*WIN);
            float win[9];
            #pragma unroll
            for (int kh = 0; kh < 3; kh++)
                #pragma unroll
                for (int kw = 0; kw < 3; kw++) {
                    int hi = ho*2-1+kh, wi = wo*2-1+kw;
                    win[kh*3+kw] = (hi>=0 && hi<HIN && wi>=0 && wi<WIN)
                                   ? pl[(hi-gi0)*WIN + wi] : 0.f;
                }
            const float* wp = wsm + ci*COUT*9;
            #pragma unroll
            for (int co = 0; co < COUT; co++) {
                float s = 0.f;
                #pragma unroll
                for (int t = 0; t < 9; t++) s += win[t]*wp[co*9+t];
                acc[co] += s;
            }
        }
        const int OHW = HOUT*WOUT;
        size_t ob = ((size_t)b * COUT) * OHW + ho*WOUT + wo;
        #pragma unroll
        for (int co = 0; co < COUT; co++)
            out[ob + (size_t)co*OHW] = fmaxf(acc[co] + bias[co], 0.f);
    }
}

// ---------------- deterministic BN stats ----------------
__global__ void bn_partial(const float* __restrict__ y, int HW, int nsl) {
    int c = blockIdx.x;
    long n = 512L * HW;
    long per = (n + nsl - 1) / nsl;
    long st = (long)blockIdx.y * per;
    long en = st + per; if (en > n) en = n;
    float s = 0.f, s2 = 0.f;
    for (long i = st + threadIdx.x; i < en; i += 256) {
        long b = i / HW, p = i % HW;
        float v = y[((size_t)b*24 + c)*HW + p];
        s += v; s2 += v*v;
    }
    __shared__ float sh[256], sh2[256];
    sh[threadIdx.x] = s; sh2[threadIdx.x] = s2;
    __syncthreads();
    for (int o = 128; o > 0; o >>= 1) {
        if (threadIdx.x < o) { sh[threadIdx.x] += sh[threadIdx.x+o]; sh2[threadIdx.x] += sh2[threadIdx.x+o]; }
        __syncthreads();
    }
    if (threadIdx.x == 0) { g_part1[c*16 + blockIdx.y] = sh[0]; g_part2[c*16 + blockIdx.y] = sh2[0]; }
}
__global__ void bn_finalize(const float* __restrict__ g, const float* __restrict__ beta,
                            int HW, int nsl) {
    int c = threadIdx.x;
    if (c >= 24) return;
    float s = 0.f, s2 = 0.f;
    for (int i = 0; i < nsl; i++) { s += g_part1[c*16+i]; s2 += g_part2[c*16+i]; }
    float n = 512.f * HW;
    float mean = s / n;
    float var = s2 / n - mean*mean;
    float sc = g[c] * rsqrtf(var + EPSV);
    g_scale[c] = sc;
    g_shift[c] = beta[c] - mean * sc;
}

// ---------------- layer-1 factorization ----------------
__global__ __launch_bounds__(256)
void uv_kernel(const float* __restrict__ x4, const float* __restrict__ qst,
               const float* __restrict__ gw1, const float* __restrict__ gb1,
               const float* __restrict__ scale, const float* __restrict__ shift,
               float* __restrict__ U, float* __restrict__ V) {
    extern __shared__ float us[];
    float* ws = us;            // 256*63
    float* xs = ws + 256*63;   // 600
    float* qs = xs + 600;      // 11
    const int b = blockIdx.x;
    const int k = threadIdx.x;

    for (int i = k; i < 256*63; i += 256) ws[i] = gw1[i];
    for (int i = k; i < 600; i += 256) {
        int ch = i / 25;
        xs[i] = x4[(size_t)b*600 + i] * scale[ch] + shift[ch];
    }
    if (k < 11) qs[k] = qst[b*11 + k];
    __syncthreads();

    const float* w = ws + k*63;
    float vq = gb1[k];
    #pragma unroll
    for (int q = 0; q < 11; q++) vq += qs[q] * w[52 + q];

    for (int pos = 0; pos < 25; pos++) {
        float cx = ((float)pos / 5.0f - 2.0f) * 0.5f;
        float cy = ((float)(pos % 5) - 2.0f) * 0.5f;
        float u = cx * w[24] + cy * w[25];
        float v = vq + cx * w[50] + cy * w[51];
        #pragma unroll
        for (int ch = 0; ch < 24; ch++) {
            float xv = xs[ch*25 + pos];
            u += xv * w[ch];
            v += xv * w[26 + ch];
        }
        U[(size_t)(b*25 + pos)*256 + k] = u;
        V[(size_t)(b*25 + pos)*256 + k] = v;
    }
}

// ---------------- fused g-chain v4: BM=64 tiles, 2 CTAs/SM ----------------
// SMEM: act 4x8KB (fp16, 64 rows x 128B swizzle) + W 2x32KB = 96KB
#define GF_SMEM_BYTES (32768 + 2*32768)   // 98304

__global__ __launch_bounds__(256, 2)
void g_fused(const float* __restrict__ U, const float* __restrict__ V,
             const __half* __restrict__ W2, const float* __restrict__ b2,
             const __half* __restrict__ W3, const float* __restrict__ b3,
             const __half* __restrict__ W4, const float* __restrict__ b4,
             float* __restrict__ Pout) {
    extern __shared__ char sm[];
    const uint32_t wBase = smem_u32(sm) + 32768;
    char* wChar = sm + 32768;

    const int tid = threadIdx.x;
    const int wid = tid >> 5, lane = tid & 31;
    const int qr = lane >> 2, qc = lane & 3;
    const int wm = (wid & 1) * 32;          // 2 m-groups of 32
    const int wn = (wid >> 1) * 64;         // 4 n-groups of 64
    const int bid = blockIdx.x;
    const int b = bid / 10, tile = bid - b*10;

    int brow[8], bj[8], bdst[8];
    #pragma unroll
    for (int it = 0; it < 8; it++) {
        int cid = it*256 + tid;
        brow[it] = cid >> 3; bj[it] = cid & 7;
        bdst[it] = brow[it]*128 + ((bj[it]*16) ^ ((brow[it] & 7) * 16));
    }

    // prefetch W2 chunks 0,1
    #pragma unroll
    for (int it = 0; it < 8; it++)
        cp_async16(wBase + bdst[it], (const char*)W2 + (size_t)brow[it]*512 + bj[it]*16);
    cp_commit();
    #pragma unroll
    for (int it = 0; it < 8; it++)
        cp_async16(wBase + 32768 + bdst[it], (const char*)W2 + (size_t)brow[it]*512 + 128 + bj[it]*16);
    cp_commit();

    // ---- build h1 tile (64 rows) into act (fp16, 128B swizzle) ----
    #pragma unroll
    for (int c = 0; c < 4; c++) {
        #pragma unroll
        for (int it = 0; it < 2; it++) {
            int idx = it*256 + tid;
            int row = idx >> 3, gq = idx & 7;
            int lr = tile*64 + row;
            uint4 val = make_uint4(0u, 0u, 0u, 0u);
            if (lr < 625) {
                int a = lr / 25, cc2 = lr - a*25;
                const float* up = U + ((size_t)(b*25 + cc2))*256 + c*64 + gq*8;
                const float* vp = V + ((size_t)(b*25 + a))*256 + c*64 + gq*8;
                float4 u0 = *(const float4*)up;
                float4 u1 = *(const float4*)(up + 4);
                float4 v0 = *(const float4*)vp;
                float4 v1 = *(const float4*)(vp + 4);
                __half2 p0 = __floats2half2_rn(fmaxf(u0.x+v0.x,0.f), fmaxf(u0.y+v0.y,0.f));
                __half2 p1 = __floats2half2_rn(fmaxf(u0.z+v0.z,0.f), fmaxf(u0.w+v0.w,0.f));
                __half2 p2 = __floats2half2_rn(fmaxf(u1.x+v1.x,0.f), fmaxf(u1.y+v1.y,0.f));
                __half2 p3 = __floats2half2_rn(fmaxf(u1.z+v1.z,0.f), fmaxf(u1.w+v1.w,0.f));
                val.x = *reinterpret_cast<uint32_t*>(&p0);
                val.y = *reinterpret_cast<uint32_t*>(&p1);
                val.z = *reinterpret_cast<uint32_t*>(&p2);
                val.w = *reinterpret_cast<uint32_t*>(&p3);
            }
            *(uint4*)(sm + c*8192 + row*128 + ((gq*16) ^ ((row & 7) * 16))) = val;
        }
    }

    float acc[2][8][4];
    #pragma unroll
    for (int mf = 0; mf < 2; mf++)
        #pragma unroll
        for (int nf = 0; nf < 8; nf++)
            #pragma unroll
            for (int i = 0; i < 4; i++) acc[mf][nf][i] = 0.f;

    const __half* Ws[3] = { W2, W3, W4 };
    const float* Bsx[3] = { b2, b3, b4 };

    #pragma unroll 1
    for (int g = 0; g < 3; g++) {
        #pragma unroll
        for (int kc = 0; kc < 4; kc++) {
            if (kc < 3) cp_wait1(); else cp_wait0();
            __syncthreads();
            const char* Ab = sm + kc*8192;
            const char* Bb = wChar + (kc & 1)*32768;
            #pragma unroll
            for (int ks = 0; ks < 4; ks++) {
                const uint32_t fa = ks*32 + qc*4;
                const uint32_t o0 = fa ^ (qr*16);
                const uint32_t o1 = (fa + 16) ^ (qr*16);
                uint32_t af[2][4];
                #pragma unroll
                for (int mf = 0; mf < 2; mf++) {
                    const char* p = Ab + (wm + mf*16 + qr)*128;
                    af[mf][0] = *(const uint32_t*)(p + o0);
                    af[mf][1] = *(const uint32_t*)(p + 1024 + o0);
                    af[mf][2] = *(const uint32_t*)(p + o1);
                    af[mf][3] = *(const uint32_t*)(p + 1024 + o1);
                }
                uint32_t bf[8][2];
                #pragma unroll
                for (int nf = 0; nf < 8; nf++) {
                    const char* p = Bb + (wn + nf*8 + qr)*128;
                    bf[nf][0] = *(const uint32_t*)(p + o0);
                    bf[nf][1] = *(const uint32_t*)(p + o1);
                }
                #pragma unroll
                for (int mf = 0; mf < 2; mf++)
                    #pragma unroll
                    for (int nf = 0; nf < 8; nf++)
                        mma_f16(acc[mf][nf], af[mf], bf[nf]);
            }
            __syncthreads();
            if (kc < 2) {
                #pragma unroll
                for (int it = 0; it < 8; it++)
                    cp_async16(wBase + (kc & 1)*32768 + bdst[it],
                               (const char*)Ws[g] + (size_t)brow[it]*512 + (kc+2)*128 + bj[it]*16);
                cp_commit();
            }
        }

        if (g < 2) {
            // prefetch next layer chunks 0,1
            #pragma unroll
            for (int it = 0; it < 8; it++)
                cp_async16(wBase + bdst[it], (const char*)Ws[g+1] + (size_t)brow[it]*512 + bj[it]*16);
            cp_commit();
            #pragma unroll
            for (int it = 0; it < 8; it++)
                cp_async16(wBase + 32768 + bdst[it], (const char*)Ws[g+1] + (size_t)brow[it]*512 + 128 + bj[it]*16);
            cp_commit();
            // writeback h = relu(acc+bias) fp16 into act (in place)
            const float* bp = Bsx[g];
            #pragma unroll
            for (int nf = 0; nf < 8; nf++) {
                int c0 = wn + nf*8 + qc*2;
                float bb0 = bp[c0], bb1 = bp[c0+1];
                int chunk = c0 >> 6;
                int fb = (c0 & 63) * 2;
                int gidx = fb >> 4, rem = fb & 15;
                #pragma unroll
                for (int mf = 0; mf < 2; mf++) {
                    int r1 = wm + mf*16 + qr;
                    int r2 = r1 + 8;
                    __half2 h0 = __floats2half2_rn(fmaxf(acc[mf][nf][0]+bb0, 0.f),
                                                   fmaxf(acc[mf][nf][1]+bb1, 0.f));
                    __half2 h1 = __floats2half2_rn(fmaxf(acc[mf][nf][2]+bb0, 0.f),
                                                   fmaxf(acc[mf][nf][3]+bb1, 0.f));
                    *(__half2*)(sm + chunk*8192 + r1*128 + ((gidx*16) ^ ((r1 & 7)*16)) + rem) = h0;
                    *(__half2*)(sm + chunk*8192 + r2*128 + ((gidx*16) ^ ((r2 & 7)*16)) + rem) = h1;
                    acc[mf][nf][0] = 0.f; acc[mf][nf][1] = 0.f;
                    acc[mf][nf][2] = 0.f; acc[mf][nf][3] = 0.f;
                }
            }
            __syncthreads();
        } else {
            // pooling epilogue over valid rows of this 64-row tile
            const int vmax = (tile < 9) ? 64 : 49;
            float* pool = (float*)wChar;
            const float* bp = Bsx[2];
            #pragma unroll
            for (int nf = 0; nf < 8; nf++) {
                int c0 = wn + nf*8 + qc*2;
                float bb0 = bp[c0], bb1 = bp[c0+1];
                float s0 = 0.f, s1 = 0.f;
                #pragma unroll
                for (int mf = 0; mf < 2; mf++) {
                    int r1 = wm + mf*16 + qr;
                    int r2 = r1 + 8;
                    if (r1 < vmax) {
                        s0 += fmaxf(acc[mf][nf][0] + bb0, 0.f);
                        s1 += fmaxf(acc[mf][nf][1] + bb1, 0.f);
                    }
                    if (r2 < vmax) {
                        s0 += fmaxf(acc[mf][nf][2] + bb0, 0.f);
                        s1 += fmaxf(acc[mf][nf][3] + bb1, 0.f);
                    }
                }
                #pragma unroll
                for (int m = 4; m <= 16; m <<= 1) {
                    s0 += __shfl_xor_sync(0xffffffffu, s0, m);
                    s1 += __shfl_xor_sync(0xffffffffu, s1, m);
                }
                if (qr == 0) {
                    pool[(wid & 1)*256 + c0] = s0;
                    pool[(wid & 1)*256 + c0 + 1] = s1;
                }
            }
            __syncthreads();
            if (tid < 256)
                Pout[(size_t)bid*256 + tid] = pool[tid] + pool[256 + tid];
        }
    }
}

// ---------------- XG reduce (10 tiles per image) ----------------
__global__ void xg_kernel(const float* __restrict__ P, float* __restrict__ XG) {
    int b = blockIdx.x, k = threadIdx.x;
    float s = 0.f;
    #pragma unroll
    for (int t = 0; t < 10; t++) s += P[(size_t)(b*10 + t)*256 + k];
    XG[b*256 + k] = s;
}

// ---------------- SIMT GEMM for tiny f-layers ----------------
template<int RELU>
__global__ void gemm_bias_kernel(const float* __restrict__ A, const float* __restrict__ W,
                                 const float* __restrict__ bias, float* __restrict__ C,
                                 int M, int N, int K) {
    __shared__ float As[16][65];
    __shared__ float Bsm[16][65];
    const int bm = blockIdx.y * 64;
    const int bn = blockIdx.x * 64;
    const int tid = threadIdx.x;
    const int tx = tid & 15;
    const int ty = tid >> 4;
    const int lrow = tid >> 2;
    const int lcol = (tid & 3) * 4;

    float acc[4][4];
    #pragma unroll
    for (int i = 0; i < 4; i++)
        #pragma unroll
        for (int j = 0; j < 4; j++) acc[i][j] = 0.f;

    for (int k0 = 0; k0 < K; k0 += 16) {
        float4 av = make_float4(0.f,0.f,0.f,0.f);
        if (bm + lrow < M) av = *(const float4*)(A + (size_t)(bm+lrow)*K + k0 + lcol);
        As[lcol+0][lrow]=av.x; As[lcol+1][lrow]=av.y; As[lcol+2][lrow]=av.z; As[lcol+3][lrow]=av.w;
        float4 bv = make_float4(0.f,0.f,0.f,0.f);
        if (bn + lrow < N) bv = *(const float4*)(W + (size_t)(bn+lrow)*K + k0 + lcol);
        Bsm[lcol+0][lrow]=bv.x; Bsm[lcol+1][lrow]=bv.y; Bsm[lcol+2][lrow]=bv.z; Bsm[lcol+3][lrow]=bv.w;
        __syncthreads();
        #pragma unroll
        for (int kk = 0; kk < 16; kk++) {
            float a[4], bb[4];
            #pragma unroll
            for (int i = 0; i < 4; i++) a[i] = As[kk][ty*4+i];
            #pragma unroll
            for (int j = 0; j < 4; j++) bb[j] = Bsm[kk][tx*4+j];
            #pragma unroll
            for (int i = 0; i < 4; i++)
                #pragma unroll
                for (int j = 0; j < 4; j++) acc[i][j] += a[i]*bb[j];
        }
        __syncthreads();
    }
    #pragma unroll
    for (int i = 0; i < 4; i++) {
        int m = bm + ty*4 + i;
        if (m >= M) continue;
        #pragma unroll
        for (int j = 0; j < 4; j++) {
            int n = bn + tx*4 + j;
            if (n >= N) continue;
            float v = acc[i][j] + bias[n];
            if (RELU) v = fmaxf(v, 0.f);
            C[(size_t)m*N + n] = v;
        }
    }
}

// ---------------- log_softmax ----------------
__global__ void logsoftmax_kernel(const float* __restrict__ in, float* __restrict__ out) {
    int b = blockIdx.x * blockDim.x + threadIdx.x;
    if (b >= 512) return;
    float v[10];
    float m = -1e30f;
    #pragma unroll
    for (int i = 0; i < 10; i++) { v[i] = in[b*10+i]; m = fmaxf(m, v[i]); }
    float s = 0.f;
    #pragma unroll
    for (int i = 0; i < 10; i++) s += expf(v[i] - m);
    float ls = logf(s) + m;
    #pragma unroll
    for (int i = 0; i < 10; i++) out[b*10+i] = v[i] - ls;
}

// ---------------- launch ----------------
extern "C" void kernel_launch(void* const* d_in, const int* in_sizes, int n_in,
                              void* d_out, int out_size) {
    const float* img  = (const float*)d_in[0];
    const float* qst  = (const float*)d_in[1];
    const float* c1w  = (const float*)d_in[2];
    const float* c1b  = (const float*)d_in[3];
    const float* bn1g = (const float*)d_in[4];
    const float* bn1b = (const float*)d_in[5];
    const float* c2w  = (const float*)d_in[6];
    const float* c2b  = (const float*)d_in[7];
    const float* bn2g = (const float*)d_in[8];
    const float* bn2b = (const float*)d_in[9];
    const float* c3w  = (const float*)d_in[10];
    const float* c3b  = (const float*)d_in[11];
    const float* bn3g = (const float*)d_in[12];
    const float* bn3b = (const float*)d_in[13];
    const float* c4w  = (const float*)d_in[14];
    const float* c4b  = (const float*)d_in[15];
    const float* bn4g = (const float*)d_in[16];
    const float* bn4b = (const float*)d_in[17];
    const float* gw1  = (const float*)d_in[18];
    const float* gb1  = (const float*)d_in[19];
    const float* gw2  = (const float*)d_in[20];
    const float* gb2  = (const float*)d_in[21];
    const float* gw3  = (const float*)d_in[22];
    const float* gb3  = (const float*)d_in[23];
    const float* gw4  = (const float*)d_in[24];
    const float* gb4  = (const float*)d_in[25];
    const float* fw1  = (const float*)d_in[26];
    const float* fb1  = (const float*)d_in[27];
    const float* fw2  = (const float*)d_in[28];
    const float* fb2  = (const float*)d_in[29];
    const float* fw3  = (const float*)d_in[30];
    const float* fb3  = (const float*)d_in[31];
    float* out = (float*)d_out;

    float *buf1,*buf2,*buf3,*buf4,*scale,*shift,*U,*V,*P,*XG,*F1,*F2,*FO;
    __half *W2h,*W3h,*W4h;
    cudaGetSymbolAddress((void**)&buf1, g_buf1);
    cudaGetSymbolAddress((void**)&buf2, g_buf2);
    cudaGetSymbolAddress((void**)&buf3, g_buf3);
    cudaGetSymbolAddress((void**)&buf4, g_buf4);
    cudaGetSymbolAddress((void**)&scale, g_scale);
    cudaGetSymbolAddress((void**)&shift, g_shift);
    cudaGetSymbolAddress((void**)&U, g_U);
    cudaGetSymbolAddress((void**)&V, g_V);
    cudaGetSymbolAddress((void**)&P, g_P);
    cudaGetSymbolAddress((void**)&XG, g_XG);
    cudaGetSymbolAddress((void**)&F1, g_F1);
    cudaGetSymbolAddress((void**)&F2, g_F2);
    cudaGetSymbolAddress((void**)&FO, g_FO);
    cudaGetSymbolAddress((void**)&W2h, g_W2h);
    cudaGetSymbolAddress((void**)&W3h, g_W3h);
    cudaGetSymbolAddress((void**)&W4h, g_W4h);

    const int C1_SMEM = (3*21*75 + 3*24*9) * 4;
    const int C2_SMEM = (24*21*38 + 24*24*9) * 4;
    const int C3_SMEM = (24*19*19 + 24*24*9) * 4;
    const int C4_SMEM = (8*24*10*10 + 24*24*9) * 4;
    const int UV_SMEM = (256*63 + 600 + 16) * 4;

    cudaFuncSetAttribute((const void*)conv_split_kernel<3,24,75,75,38,38,384,4,0,0>,
                         cudaFuncAttributeMaxDynamicSharedMemorySize, C1_SMEM);
    cudaFuncSetAttribute((const void*)conv_split_kernel<24,24,38,38,19,19,384,2,1,1>,
                         cudaFuncAttributeMaxDynamicSharedMemorySize, C2_SMEM);
    cudaFuncSetAttribute((const void*)conv_res_kernel<24,24,19,19,10,10,256,1,1,1>,
                         cudaFuncAttributeMaxDynamicSharedMemorySize, C3_SMEM);
    cudaFuncSetAttribute((const void*)conv_res_kernel<24,24,10,10,5,5,256,1,1,8>,
                         cudaFuncAttributeMaxDynamicSharedMemorySize, C4_SMEM);
    cudaFuncSetAttribute((const void*)uv_kernel,
                         cudaFuncAttributeMaxDynamicSharedMemorySize, UV_SMEM);
    cudaFuncSetAttribute((const void*)g_fused,
                         cudaFuncAttributeMaxDynamicSharedMemorySize, GF_SMEM_BYTES);

    w_to_half3<<<768, 256>>>(gw2, gw3, gw4, W2h, W3h, W4h);

    conv_split_kernel<3,24,75,75,38,38,384,4,0,0><<<dim3(512,4),384,C1_SMEM>>>(
        img, c1w, c1b, scale, shift, buf1);
    bn_partial<<<dim3(24,16),256>>>(buf1, 38*38, 16);
    bn_finalize<<<1,32>>>(bn1g, bn1b, 38*38, 16);

    conv_split_kernel<24,24,38,38,19,19,384,2,1,1><<<dim3(512,2),384,C2_SMEM>>>(
        buf1, c2w, c2b, scale, shift, buf2);
    bn_partial<<<dim3(24,8),256>>>(buf2, 19*19, 8);
    bn_finalize<<<1,32>>>(bn2g, bn2b, 19*19, 8);

    conv_res_kernel<24,24,19,19,10,10,256,1,1,1><<<512,256,C3_SMEM>>>(
        buf2, c3w, c3b, scale, shift, buf3);
    bn_partial<<<dim3(24,4),256>>>(buf3, 10*10, 4);
    bn_finalize<<<1,32>>>(bn3g, bn3b, 10*10, 4);

    conv_res_kernel<24,24,10,10,5,5,256,1,1,8><<<64,256,C4_SMEM>>>(
        buf3, c4w, c4b, scale, shift, buf4);
    bn_partial<<<dim3(24,2),256>>>(buf4, 5*5, 2);
    bn_finalize<<<1,32>>>(bn4g, bn4b, 5*5, 2);

    uv_kernel<<<512, 256, UV_SMEM>>>(buf4, qst, gw1, gb1, scale, shift, U, V);

    g_fused<<<5120, 256, GF_SMEM_BYTES>>>(U, V, W2h, gb2, W3h, gb3, W4h, gb4, P);
    xg_kernel<<<512, 256>>>(P, XG);

    {
        dim3 grid(4, 8), block(256);
        gemm_bias_kernel<1><<<grid, block>>>(XG, fw1, fb1, F1, 512, 256, 256);
        gemm_bias_kernel<1><<<grid, block>>>(F1, fw2, fb2, F2, 512, 256, 256);
        dim3 grid3(1, 8);
        gemm_bias_kernel<0><<<grid3, block>>>(F2, fw3, fb3, FO, 512, 10, 256);
    }

    logsoftmax_kernel<<<2, 256>>>(FO, out);
}

// round 16
// speedup vs baseline: 1.0078x; 1.0078x over previous
#include <cuda_runtime.h>
#include <cuda_fp16.h>
#include <math.h>
#include <stdint.h>

#define EPSV 1e-5f

// ---------------- static scratch ----------------
__device__ float g_buf1[512*24*38*38];
__device__ float g_buf2[512*24*19*19];
__device__ float g_buf3[512*24*10*10];
__device__ float g_buf4[512*24*5*5];
__device__ float g_part1[24*16];
__device__ float g_part2[24*16];
__device__ float g_scale[24];
__device__ float g_shift[24];
__device__ int   g_ctr;
__device__ float g_U[512*25*256];
__device__ float g_V[512*25*256];
__device__ __half g_W2h[65536];
__device__ __half g_W3h[65536];
__device__ __half g_W4h[65536];
__device__ float g_P[5120*256];
__device__ float g_XG[512*256];
__device__ float g_F1[512*256];
__device__ float g_F2[512*256];
__device__ float g_FO[512*10];

// ---------------- helpers ----------------
__device__ __forceinline__ uint32_t smem_u32(const void* p) {
    uint32_t a;
    asm("{ .reg .u64 t; cvta.to.shared.u64 t, %1; cvt.u32.u64 %0, t; }" : "=r"(a) : "l"(p));
    return a;
}
__device__ __forceinline__ void cp_async16(uint32_t dst, const void* src) {
    asm volatile("cp.async.cg.shared.global [%0], [%1], 16;" :: "r"(dst), "l"(src));
}
__device__ __forceinline__ void cp_commit() { asm volatile("cp.async.commit_group;"); }
__device__ __forceinline__ void cp_wait0() { asm volatile("cp.async.wait_group 0;"); }
__device__ __forceinline__ void cp_wait1() { asm volatile("cp.async.wait_group 1;"); }

__device__ __forceinline__ void mma_f16(float* d, const uint32_t* a, const uint32_t* b) {
    asm volatile(
        "mma.sync.aligned.m16n8k16.row.col.f32.f16.f16.f32 "
        "{%0,%1,%2,%3}, {%4,%5,%6,%7}, {%8,%9}, {%0,%1,%2,%3};"
        : "+f"(d[0]), "+f"(d[1]), "+f"(d[2]), "+f"(d[3])
        : "r"(a[0]), "r"(a[1]), "r"(a[2]), "r"(a[3]), "r"(b[0]), "r"(b[1]));
}

// ---------------- weight conversion fp32 -> fp16 (one launch) ----------------
__global__ void w_to_half3(const float* __restrict__ a, const float* __restrict__ b,
                           const float* __restrict__ c,
                           __half* __restrict__ oa, __half* __restrict__ ob,
                           __half* __restrict__ oc) {
    int i = blockIdx.x * blockDim.x + threadIdx.x;
    if (i >= 3*65536) return;
    const float* src = (i < 65536) ? a : ((i < 131072) ? b : c);
    __half* dst = (i < 65536) ? oa : ((i < 131072) ? ob : oc);
    int off = i & 65535;
    dst[off] = __float2half_rn(src[off]);
}

// ---------------- conv: all planes resident, co-split ----------------
template<int CIN,int COUT,int HIN,int WIN,int HOUT,int WOUT,int NTHR,int BNIN,int IMGS,int COSPLIT>
__global__ __launch_bounds__(NTHR)
void conv_res_kernel(const float* __restrict__ in, const float* __restrict__ w,
                     const float* __restrict__ bias,
                     const float* __restrict__ scale, const float* __restrict__ shift,
                     float* __restrict__ out) {
    extern __shared__ float cs[];
    float* planes = cs;
    float* wsm = cs + IMGS*CIN*HIN*WIN;
    const int tid = threadIdx.x;
    const int HW = HIN*WIN;
    const size_t gbase = (size_t)blockIdx.x * IMGS * CIN * HW;

    for (int i = tid; i < IMGS*CIN*HW; i += NTHR) {
        float v = in[gbase + i];
        if (BNIN) { int ci = (i / HW) % CIN; v = v*scale[ci] + shift[ci]; }
        planes[i] = v;
    }
    for (int i = tid; i < CIN*COUT*9; i += NTHR) {
        int ci = i / (COUT*9); int r = i % (COUT*9); int co = r/9, t = r%9;
        wsm[i] = w[(co*CIN+ci)*9 + t];
    }
    __syncthreads();

    const int OHW = HOUT*WOUT;
    const int NOUT = IMGS*OHW;
    constexpr int CO = COUT / COSPLIT;
    if (tid < NOUT*COSPLIT) {
        int pos = tid % NOUT, ch = tid / NOUT;
        int im = pos / OHW, pp = pos % OHW;
        int ho = pp / WOUT, wo = pp % WOUT;
        const float* pl = planes + im*CIN*HW;
        float acc[CO];
        #pragma unroll
        for (int co = 0; co < CO; co++) acc[co] = 0.f;
        for (int ci = 0; ci < CIN; ci++) {
            float win[9];
            #pragma unroll
            for (int kh = 0; kh < 3; kh++)
                #pragma unroll
                for (int kw = 0; kw < 3; kw++) {
                    int hi = ho*2-1+kh, wi = wo*2-1+kw;
                    win[kh*3+kw] = (hi>=0 && hi<HIN && wi>=0 && wi<WIN)
                                   ? pl[ci*HW + hi*WIN + wi] : 0.f;
                }
            const float* wp = wsm + ci*COUT*9 + ch*CO*9;
            #pragma unroll
            for (int co = 0; co < CO; co++) {
                float s = 0.f;
                #pragma unroll
                for (int t = 0; t < 9; t++) s += win[t]*wp[co*9+t];
                acc[co] += s;
            }
        }
        size_t ob = ((size_t)(blockIdx.x*IMGS + im) * COUT + ch*CO) * OHW + pp;
        #pragma unroll
        for (int co = 0; co < CO; co++)
            out[ob + (size_t)co*OHW] = fmaxf(acc[co] + bias[ch*CO + co], 0.f);
    }
}

// ---------------- conv row-split: SPLITS CTAs per image, co-split threads ----------------
template<int CIN,int COUT,int HIN,int WIN,int HOUT,int WOUT,int NTHR,int SPLITS,int BNIN,int VEC,int COSPLIT>
__global__ __launch_bounds__(NTHR, 2)
void conv_split_kernel(const float* __restrict__ in, const float* __restrict__ w,
                       const float* __restrict__ bias,
                       const float* __restrict__ scale, const float* __restrict__ shift,
                       float* __restrict__ out) {
    constexpr int CEILR = (HOUT + SPLITS - 1) / SPLITS;
    constexpr int MAXR = 2*CEILR + 1;
    extern __shared__ float cs[];
    float* planes = cs;                      // CIN*MAXR*WIN
    float* wsm = cs + CIN*MAXR*WIN;          // CIN*COUT*9
    const int tid = threadIdx.x;
    const int b = blockIdx.x;
    const int sp = blockIdx.y;
    const int r0 = sp * CEILR;
    const int r1 = (r0 + CEILR < HOUT) ? (r0 + CEILR) : HOUT;
    const int gi0 = (2*r0 - 1 > 0) ? (2*r0 - 1) : 0;
    const int gi1 = (2*r1 < HIN) ? (2*r1) : HIN;
    const int NR = gi1 - gi0;
    const int HW = HIN*WIN;
    const int NRW = NR * WIN;

    const float* src0 = in + (size_t)b*CIN*HW + gi0*WIN;
    if (VEC) {
        const int NRW2 = NRW >> 1;
        for (int i = tid; i < CIN*NRW2; i += NTHR) {
            int ci = i / NRW2, rem = i - ci*NRW2;
            float2 v = *(const float2*)(src0 + (size_t)ci*HW + rem*2);
            if (BNIN) {
                float sc = scale[ci], sh = shift[ci];
                v.x = v.x*sc + sh; v.y = v.y*sc + sh;
            }
            *(float2*)(planes + ci*(MAXR*WIN) + rem*2) = v;
        }
    } else {
        for (int i = tid; i < CIN*NRW; i += NTHR) {
            int ci = i / NRW, rem = i - ci*NRW;
            float v = src0[(size_t)ci*HW + rem];
            if (BNIN) v = v*scale[ci] + shift[ci];
            planes[ci*(MAXR*WIN) + rem] = v;
        }
    }
    for (int i = tid; i < CIN*COUT*9; i += NTHR) {
        int ci = i / (COUT*9); int r = i % (COUT*9); int co = r/9, t = r%9;
        wsm[i] = w[(co*CIN+ci)*9 + t];
    }
    __syncthreads();

    const int nout = (r1 - r0) * WOUT;
    constexpr int CO = COUT / COSPLIT;
    if (tid < nout*COSPLIT) {
        int pos = tid % nout, ch = tid / nout;
        int ho = r0 + pos / WOUT, wo = pos % WOUT;
        float acc[CO];
        #pragma unroll
        for (int co = 0; co < CO; co++) acc[co] = 0.f;
        for (int ci = 0; ci < CIN; ci++) {
            const float* pl = planes + ci*(MAXR*WIN);
            float win[9];
            #pragma unroll
            for (int kh = 0; kh < 3; kh++)
                #pragma unroll
                for (int kw = 0; kw < 3; kw++) {
                    int hi = ho*2-1+kh, wi = wo*2-1+kw;
                    win[kh*3+kw] = (hi>=0 && hi<HIN && wi>=0 && wi<WIN)
                                   ? pl[(hi-gi0)*WIN + wi] : 0.f;
                }
            const float* wp = wsm + ci*COUT*9 + ch*CO*9;
            #pragma unroll
            for (int co = 0; co < CO; co++) {
                float s = 0.f;
                #pragma unroll
                for (int t = 0; t < 9; t++) s += win[t]*wp[co*9+t];
                acc[co] += s;
            }
        }
        const int OHW = HOUT*WOUT;
        size_t ob = ((size_t)b * COUT + ch*CO) * OHW + ho*WOUT + wo;
        #pragma unroll
        for (int co = 0; co < CO; co++)
            out[ob + (size_t)co*OHW] = fmaxf(acc[co] + bias[ch*CO + co], 0.f);
    }
}

// ---------------- BN stats with fused finalize (last-block election) ----------------
__global__ void bn_stats(const float* __restrict__ y, int HW, int nsl,
                         const float* __restrict__ g, const float* __restrict__ beta) {
    int c = blockIdx.x;
    long n = 512L * HW;
    long per = (n + nsl - 1) / nsl;
    long st = (long)blockIdx.y * per;
    long en = st + per; if (en > n) en = n;
    float s = 0.f, s2 = 0.f;
    for (long i = st + threadIdx.x; i < en; i += 256) {
        long b = i / HW, p = i % HW;
        float v = y[((size_t)b*24 + c)*HW + p];
        s += v; s2 += v*v;
    }
    __shared__ float sh[256], sh2[256];
    __shared__ int last;
    sh[threadIdx.x] = s; sh2[threadIdx.x] = s2;
    __syncthreads();
    for (int o = 128; o > 0; o >>= 1) {
        if (threadIdx.x < o) { sh[threadIdx.x] += sh[threadIdx.x+o]; sh2[threadIdx.x] += sh2[threadIdx.x+o]; }
        __syncthreads();
    }
    if (threadIdx.x == 0) {
        g_part1[c*16 + blockIdx.y] = sh[0];
        g_part2[c*16 + blockIdx.y] = sh2[0];
        __threadfence();
        int old = atomicAdd(&g_ctr, 1);
        last = (old == 24*nsl - 1) ? 1 : 0;
    }
    __syncthreads();
    if (last) {
        __threadfence();   // acquire: partials visible
        if (threadIdx.x < 24) {
            int cc = threadIdx.x;
            float ss = 0.f, ss2 = 0.f;
            for (int i = 0; i < nsl; i++) { ss += g_part1[cc*16+i]; ss2 += g_part2[cc*16+i]; }
            float mean = ss / (float)n;
            float var = ss2 / (float)n - mean*mean;
            float sc = g[cc] * rsqrtf(var + EPSV);
            g_scale[cc] = sc;
            g_shift[cc] = beta[cc] - mean * sc;
        }
        __syncthreads();
        if (threadIdx.x == 0) { __threadfence(); g_ctr = 0; }
    }
}

// ---------------- layer-1 factorization ----------------
__global__ __launch_bounds__(256)
void uv_kernel(const float* __restrict__ x4, const float* __restrict__ qst,
               const float* __restrict__ gw1, const float* __restrict__ gb1,
               const float* __restrict__ scale, const float* __restrict__ shift,
               float* __restrict__ U, float* __restrict__ V) {
    extern __shared__ float us[];
    float* ws = us;            // 256*63
    float* xs = ws + 256*63;   // 600
    float* qs = xs + 600;      // 11
    const int b = blockIdx.x;
    const int k = threadIdx.x;

    for (int i = k; i < 256*63; i += 256) ws[i] = gw1[i];
    for (int i = k; i < 600; i += 256) {
        int ch = i / 25;
        xs[i] = x4[(size_t)b*600 + i] * scale[ch] + shift[ch];
    }
    if (k < 11) qs[k] = qst[b*11 + k];
    __syncthreads();

    const float* w = ws + k*63;
    float vq = gb1[k];
    #pragma unroll
    for (int q = 0; q < 11; q++) vq += qs[q] * w[52 + q];

    for (int pos = 0; pos < 25; pos++) {
        float cx = ((float)pos / 5.0f - 2.0f) * 0.5f;
        float cy = ((float)(pos % 5) - 2.0f) * 0.5f;
        float u = cx * w[24] + cy * w[25];
        float v = vq + cx * w[50] + cy * w[51];
        #pragma unroll
        for (int ch = 0; ch < 24; ch++) {
            float xv = xs[ch*25 + pos];
            u += xv * w[ch];
            v += xv * w[26 + ch];
        }
        U[(size_t)(b*25 + pos)*256 + k] = u;
        V[(size_t)(b*25 + pos)*256 + k] = v;
    }
}

// ---------------- fused g-chain (frozen round-6 structure, BM=128) ----------------
#define GF_SMEM_BYTES (65536 + 2*32768)   // 131072

__global__ __launch_bounds__(256)
void g_fused(const float* __restrict__ U, const float* __restrict__ V,
             const __half* __restrict__ W2, const float* __restrict__ b2,
             const __half* __restrict__ W3, const float* __restrict__ b3,
             const __half* __restrict__ W4, const float* __restrict__ b4,
             float* __restrict__ Pout) {
    extern __shared__ char sm[];
    const uint32_t wBase = smem_u32(sm) + 65536;
    char* wChar = sm + 65536;

    const int tid = threadIdx.x;
    const int wid = tid >> 5, lane = tid & 31;
    const int qr = lane >> 2, qc = lane & 3;
    const int wm = (wid & 1) * 64;
    const int wn = (wid >> 1) * 64;
    const int bid = blockIdx.x;
    const int b = bid / 5, tile = bid - b*5;

    int brow[8], bj[8], bdst[8];
    #pragma unroll
    for (int it = 0; it < 8; it++) {
        int cid = it*256 + tid;
        brow[it] = cid >> 3; bj[it] = cid & 7;
        bdst[it] = brow[it]*128 + ((bj[it]*16) ^ ((brow[it] & 7) * 16));
    }

    #pragma unroll
    for (int it = 0; it < 8; it++)
        cp_async16(wBase + bdst[it], (const char*)W2 + (size_t)brow[it]*512 + bj[it]*16);
    cp_commit();
    #pragma unroll
    for (int it = 0; it < 8; it++)
        cp_async16(wBase + 32768 + bdst[it], (const char*)W2 + (size_t)brow[it]*512 + 128 + bj[it]*16);
    cp_commit();

    #pragma unroll
    for (int c = 0; c < 4; c++) {
        #pragma unroll
        for (int it = 0; it < 4; it++) {
            int idx = it*256 + tid;
            int row = idx >> 3, gq = idx & 7;
            int lr = tile*128 + row;
            uint4 val = make_uint4(0u, 0u, 0u, 0u);
            if (lr < 625) {
                int a = lr / 25, cc2 = lr - a*25;
                const float* up = U + ((size_t)(b*25 + cc2))*256 + c*64 + gq*8;
                const float* vp = V + ((size_t)(b*25 + a))*256 + c*64 + gq*8;
                float4 u0 = *(const float4*)up;
                float4 u1 = *(const float4*)(up + 4);
                float4 v0 = *(const float4*)vp;
                float4 v1 = *(const float4*)(vp + 4);
                __half2 p0 = __floats2half2_rn(fmaxf(u0.x+v0.x,0.f), fmaxf(u0.y+v0.y,0.f));
                __half2 p1 = __floats2half2_rn(fmaxf(u0.z+v0.z,0.f), fmaxf(u0.w+v0.w,0.f));
                __half2 p2 = __floats2half2_rn(fmaxf(u1.x+v1.x,0.f), fmaxf(u1.y+v1.y,0.f));
                __half2 p3 = __floats2half2_rn(fmaxf(u1.z+v1.z,0.f), fmaxf(u1.w+v1.w,0.f));
                val.x = *reinterpret_cast<uint32_t*>(&p0);
                val.y = *reinterpret_cast<uint32_t*>(&p1);
                val.z = *reinterpret_cast<uint32_t*>(&p2);
                val.w = *reinterpret_cast<uint32_t*>(&p3);
            }
            *(uint4*)(sm + c*16384 + row*128 + ((gq*16) ^ ((row & 7) * 16))) = val;
        }
    }

    float acc[4][8][4];
    #pragma unroll
    for (int mf = 0; mf < 4; mf++)
        #pragma unroll
        for (int nf = 0; nf < 8; nf++)
            #pragma unroll
            for (int i = 0; i < 4; i++) acc[mf][nf][i] = 0.f;

    const __half* Ws[3] = { W2, W3, W4 };
    const float* Bsx[3] = { b2, b3, b4 };

    #pragma unroll 1
    for (int g = 0; g < 3; g++) {
        #pragma unroll
        for (int kc = 0; kc < 4; kc++) {
            if (kc < 3) cp_wait1(); else cp_wait0();
            __syncthreads();
            const char* Ab = sm + kc*16384;
            const char* Bb = wChar + (kc & 1)*32768;
            #pragma unroll
            for (int ks = 0; ks < 4; ks++) {
                const uint32_t fa = ks*32 + qc*4;
                const uint32_t o0 = fa ^ (qr*16);
                const uint32_t o1 = (fa + 16) ^ (qr*16);
                uint32_t af[4][4];
                #pragma unroll
                for (int mf = 0; mf < 4; mf++) {
                    const char* p = Ab + (wm + mf*16 + qr)*128;
                    af[mf][0] = *(const uint32_t*)(p + o0);
                    af[mf][1] = *(const uint32_t*)(p + 1024 + o0);
                    af[mf][2] = *(const uint32_t*)(p + o1);
                    af[mf][3] = *(const uint32_t*)(p + 1024 + o1);
                }
                uint32_t bf[8][2];
                #pragma unroll
                for (int nf = 0; nf < 8; nf++) {
                    const char* p = Bb + (wn + nf*8 + qr)*128;
                    bf[nf][0] = *(const uint32_t*)(p + o0);
                    bf[nf][1] = *(const uint32_t*)(p + o1);
                }
                #pragma unroll
                for (int mf = 0; mf < 4; mf++)
                    #pragma unroll
                    for (int nf = 0; nf < 8; nf++)
                        mma_f16(acc[mf][nf], af[mf], bf[nf]);
            }
            __syncthreads();
            if (kc < 2) {
                #pragma unroll
                for (int it = 0; it < 8; it++)
                    cp_async16(wBase + (kc & 1)*32768 + bdst[it],
                               (const char*)Ws[g] + (size_t)brow[it]*512 + (kc+2)*128 + bj[it]*16);
                cp_commit();
            }
        }

        if (g < 2) {
            #pragma unroll
            for (int it = 0; it < 8; it++)
                cp_async16(wBase + bdst[it], (const char*)Ws[g+1] + (size_t)brow[it]*512 + bj[it]*16);
            cp_commit();
            #pragma unroll
            for (int it = 0; it < 8; it++)
                cp_async16(wBase + 32768 + bdst[it], (const char*)Ws[g+1] + (size_t)brow[it]*512 + 128 + bj[it]*16);
            cp_commit();
            const float* bp = Bsx[g];
            #pragma unroll
            for (int nf = 0; nf < 8; nf++) {
                int c0 = wn + nf*8 + qc*2;
                float bb0 = bp[c0], bb1 = bp[c0+1];
                int chunk = c0 >> 6;
                int fb = (c0 & 63) * 2;
                int gidx = fb >> 4, rem = fb & 15;
                #pragma unroll
                for (int mf = 0; mf < 4; mf++) {
                    int r1 = wm + mf*16 + qr;
                    int r2 = r1 + 8;
                    __half2 h0 = __floats2half2_rn(fmaxf(acc[mf][nf][0]+bb0, 0.f),
                                                   fmaxf(acc[mf][nf][1]+bb1, 0.f));
                    __half2 h1 = __floats2half2_rn(fmaxf(acc[mf][nf][2]+bb0, 0.f),
                                                   fmaxf(acc[mf][nf][3]+bb1, 0.f));
                    *(__half2*)(sm + chunk*16384 + r1*128 + ((gidx*16) ^ ((r1 & 7)*16)) + rem) = h0;
                    *(__half2*)(sm + chunk*16384 + r2*128 + ((gidx*16) ^ ((r2 & 7)*16)) + rem) = h1;
                    acc[mf][nf][0] = 0.f; acc[mf][nf][1] = 0.f;
                    acc[mf][nf][2] = 0.f; acc[mf][nf][3] = 0.f;
                }
            }
            __syncthreads();
        } else {
            const int vmax = (tile < 4) ? 128 : 113;
            float* pool = (float*)wChar;
            const float* bp = Bsx[2];
            #pragma unroll
            for (int nf = 0; nf < 8; nf++) {
                int c0 = wn + nf*8 + qc*2;
                float bb0 = bp[c0], bb1 = bp[c0+1];
                float s0 = 0.f, s1 = 0.f;
                #pragma unroll
                for (int mf = 0; mf < 4; mf++) {
                    int r1 = wm + mf*16 + qr;
                    int r2 = r1 + 8;
                    if (r1 < vmax) {
                        s0 += fmaxf(acc[mf][nf][0] + bb0, 0.f);
                        s1 += fmaxf(acc[mf][nf][1] + bb1, 0.f);
                    }
                    if (r2 < vmax) {
                        s0 += fmaxf(acc[mf][nf][2] + bb0, 0.f);
                        s1 += fmaxf(acc[mf][nf][3] + bb1, 0.f);
                    }
                }
                #pragma unroll
                for (int m = 4; m <= 16; m <<= 1) {
                    s0 += __shfl_xor_sync(0xffffffffu, s0, m);
                    s1 += __shfl_xor_sync(0xffffffffu, s1, m);
                }
                if (qr == 0) {
                    pool[(wid & 1)*256 + c0] = s0;
                    pool[(wid & 1)*256 + c0 + 1] = s1;
                }
            }
            __syncthreads();
            if (tid < 256)
                Pout[(size_t)bid*256 + tid] = pool[tid] + pool[256 + tid];
        }
    }
}

// ---------------- XG reduce (5 tiles per image) ----------------
__global__ void xg_kernel(const float* __restrict__ P, float* __restrict__ XG) {
    int b = blockIdx.x, k = threadIdx.x;
    float s = 0.f;
    #pragma unroll
    for (int t = 0; t < 5; t++) s += P[(size_t)(b*5 + t)*256 + k];
    XG[b*256 + k] = s;
}

// ---------------- SIMT GEMM for tiny f-layers ----------------
template<int RELU>
__global__ void gemm_bias_kernel(const float* __restrict__ A, const float* __restrict__ W,
                                 const float* __restrict__ bias, float* __restrict__ C,
                                 int M, int N, int K) {
    __shared__ float As[16][65];
    __shared__ float Bsm[16][65];
    const int bm = blockIdx.y * 64;
    const int bn = blockIdx.x * 64;
    const int tid = threadIdx.x;
    const int tx = tid & 15;
    const int ty = tid >> 4;
    const int lrow = tid >> 2;
    const int lcol = (tid & 3) * 4;

    float acc[4][4];
    #pragma unroll
    for (int i = 0; i < 4; i++)
        #pragma unroll
        for (int j = 0; j < 4; j++) acc[i][j] = 0.f;

    for (int k0 = 0; k0 < K; k0 += 16) {
        float4 av = make_float4(0.f,0.f,0.f,0.f);
        if (bm + lrow < M) av = *(const float4*)(A + (size_t)(bm+lrow)*K + k0 + lcol);
        As[lcol+0][lrow]=av.x; As[lcol+1][lrow]=av.y; As[lcol+2][lrow]=av.z; As[lcol+3][lrow]=av.w;
        float4 bv = make_float4(0.f,0.f,0.f,0.f);
        if (bn + lrow < N) bv = *(const float4*)(W + (size_t)(bn+lrow)*K + k0 + lcol);
        Bsm[lcol+0][lrow]=bv.x; Bsm[lcol+1][lrow]=bv.y; Bsm[lcol+2][lrow]=bv.z; Bsm[lcol+3][lrow]=bv.w;
        __syncthreads();
        #pragma unroll
        for (int kk = 0; kk < 16; kk++) {
            float a[4], bb[4];
            #pragma unroll
            for (int i = 0; i < 4; i++) a[i] = As[kk][ty*4+i];
            #pragma unroll
            for (int j = 0; j < 4; j++) bb[j] = Bsm[kk][tx*4+j];
            #pragma unroll
            for (int i = 0; i < 4; i++)
                #pragma unroll
                for (int j = 0; j < 4; j++) acc[i][j] += a[i]*bb[j];
        }
        __syncthreads();
    }
    #pragma unroll
    for (int i = 0; i < 4; i++) {
        int m = bm + ty*4 + i;
        if (m >= M) continue;
        #pragma unroll
        for (int j = 0; j < 4; j++) {
            int n = bn + tx*4 + j;
            if (n >= N) continue;
            float v = acc[i][j] + bias[n];
            if (RELU) v = fmaxf(v, 0.f);
            C[(size_t)m*N + n] = v;
        }
    }
}

// ---------------- log_softmax ----------------
__global__ void logsoftmax_kernel(const float* __restrict__ in, float* __restrict__ out) {
    int b = blockIdx.x * blockDim.x + threadIdx.x;
    if (b >= 512) return;
    float v[10];
    float m = -1e30f;
    #pragma unroll
    for (int i = 0; i < 10; i++) { v[i] = in[b*10+i]; m = fmaxf(m, v[i]); }
    float s = 0.f;
    #pragma unroll
    for (int i = 0; i < 10; i++) s += expf(v[i] - m);
    float ls = logf(s) + m;
    #pragma unroll
    for (int i = 0; i < 10; i++) out[b*10+i] = v[i] - ls;
}

// ---------------- launch ----------------
extern "C" void kernel_launch(void* const* d_in, const int* in_sizes, int n_in,
                              void* d_out, int out_size) {
    const float* img  = (const float*)d_in[0];
    const float* qst  = (const float*)d_in[1];
    const float* c1w  = (const float*)d_in[2];
    const float* c1b  = (const float*)d_in[3];
    const float* bn1g = (const float*)d_in[4];
    const float* bn1b = (const float*)d_in[5];
    const float* c2w  = (const float*)d_in[6];
    const float* c2b  = (const float*)d_in[7];
    const float* bn2g = (const float*)d_in[8];
    const float* bn2b = (const float*)d_in[9];
    const float* c3w  = (const float*)d_in[10];
    const float* c3b  = (const float*)d_in[11];
    const float* bn3g = (const float*)d_in[12];
    const float* bn3b = (const float*)d_in[13];
    const float* c4w  = (const float*)d_in[14];
    const float* c4b  = (const float*)d_in[15];
    const float* bn4g = (const float*)d_in[16];
    const float* bn4b = (const float*)d_in[17];
    const float* gw1  = (const float*)d_in[18];
    const float* gb1  = (const float*)d_in[19];
    const float* gw2  = (const float*)d_in[20];
    const float* gb2  = (const float*)d_in[21];
    const float* gw3  = (const float*)d_in[22];
    const float* gb3  = (const float*)d_in[23];
    const float* gw4  = (const float*)d_in[24];
    const float* gb4  = (const float*)d_in[25];
    const float* fw1  = (const float*)d_in[26];
    const float* fb1  = (const float*)d_in[27];
    const float* fw2  = (const float*)d_in[28];
    const float* fb2  = (const float*)d_in[29];
    const float* fw3  = (const float*)d_in[30];
    const float* fb3  = (const float*)d_in[31];
    float* out = (float*)d_out;

    float *buf1,*buf2,*buf3,*buf4,*scale,*shift,*U,*V,*P,*XG,*F1,*F2,*FO;
    __half *W2h,*W3h,*W4h;
    cudaGetSymbolAddress((void**)&buf1, g_buf1);
    cudaGetSymbolAddress((void**)&buf2, g_buf2);
    cudaGetSymbolAddress((void**)&buf3, g_buf3);
    cudaGetSymbolAddress((void**)&buf4, g_buf4);
    cudaGetSymbolAddress((void**)&scale, g_scale);
    cudaGetSymbolAddress((void**)&shift, g_shift);
    cudaGetSymbolAddress((void**)&U, g_U);
    cudaGetSymbolAddress((void**)&V, g_V);
    cudaGetSymbolAddress((void**)&P, g_P);
    cudaGetSymbolAddress((void**)&XG, g_XG);
    cudaGetSymbolAddress((void**)&F1, g_F1);
    cudaGetSymbolAddress((void**)&F2, g_F2);
    cudaGetSymbolAddress((void**)&FO, g_FO);
    cudaGetSymbolAddress((void**)&W2h, g_W2h);
    cudaGetSymbolAddress((void**)&W3h, g_W3h);
    cudaGetSymbolAddress((void**)&W4h, g_W4h);

    const int C1_SMEM = (3*21*75 + 3*24*9) * 4;
    const int C2_SMEM = (24*21*38 + 24*24*9) * 4;   // 97344
    const int C3_SMEM = (24*19*19 + 24*24*9) * 4;   // 55392
    const int C4_SMEM = (8*24*10*10 + 24*24*9) * 4;
    const int UV_SMEM = (256*63 + 600 + 16) * 4;

    cudaFuncSetAttribute((const void*)conv_split_kernel<3,24,75,75,38,38,384,4,0,0,1>,
                         cudaFuncAttributeMaxDynamicSharedMemorySize, C1_SMEM);
    cudaFuncSetAttribute((const void*)conv_split_kernel<24,24,38,38,19,19,384,2,1,1,2>,
                         cudaFuncAttributeMaxDynamicSharedMemorySize, C2_SMEM);
    cudaFuncSetAttribute((const void*)conv_res_kernel<24,24,19,19,10,10,256,1,1,2>,
                         cudaFuncAttributeMaxDynamicSharedMemorySize, C3_SMEM);
    cudaFuncSetAttribute((const void*)conv_res_kernel<24,24,10,10,5,5,256,1,8,1>,
                         cudaFuncAttributeMaxDynamicSharedMemorySize, C4_SMEM);
    cudaFuncSetAttribute((const void*)uv_kernel,
                         cudaFuncAttributeMaxDynamicSharedMemorySize, UV_SMEM);
    cudaFuncSetAttribute((const void*)g_fused,
                         cudaFuncAttributeMaxDynamicSharedMemorySize, GF_SMEM_BYTES);

    w_to_half3<<<768, 256>>>(gw2, gw3, gw4, W2h, W3h, W4h);

    conv_split_kernel<3,24,75,75,38,38,384,4,0,0,1><<<dim3(512,4),384,C1_SMEM>>>(
        img, c1w, c1b, scale, shift, buf1);
    bn_stats<<<dim3(24,16),256>>>(buf1, 38*38, 16, bn1g, bn1b);

    conv_split_kernel<24,24,38,38,19,19,384,2,1,1,2><<<dim3(512,2),384,C2_SMEM>>>(
        buf1, c2w, c2b, scale, shift, buf2);
    bn_stats<<<dim3(24,8),256>>>(buf2, 19*19, 8, bn2g, bn2b);

    conv_res_kernel<24,24,19,19,10,10,256,1,1,2><<<512,256,C3_SMEM>>>(
        buf2, c3w, c3b, scale, shift, buf3);
    bn_stats<<<dim3(24,4),256>>>(buf3, 10*10, 4, bn3g, bn3b);

    conv_res_kernel<24,24,10,10,5,5,256,1,8,1><<<64,256,C4_SMEM>>>(
        buf3, c4w, c4b, scale, shift, buf4);
    bn_stats<<<dim3(24,2),256>>>(buf4, 5*5, 2, bn4g, bn4b);

    uv_kernel<<<512, 256, UV_SMEM>>>(buf4, qst, gw1, gb1, scale, shift, U, V);

    g_fused<<<2560, 256, GF_SMEM_BYTES>>>(U, V, W2h, gb2, W3h, gb3, W4h, gb4, P);
    xg_kernel<<<512, 256>>>(P, XG);

    {
        dim3 grid(4, 8), block(256);
        gemm_bias_kernel<1><<<grid, block>>>(XG, fw1, fb1, F1, 512, 256, 256);
        gemm_bias_kernel<1><<<grid, block>>>(F1, fw2, fb2, F2, 512, 256, 256);
        dim3 grid3(1, 8);
        gemm_bias_kernel<0><<<grid3, block>>>(F2, fw3, fb3, FO, 512, 10, 256);
    }

    logsoftmax_kernel<<<2, 256>>>(FO, out);
}